// round 2
// baseline (speedup 1.0000x reference)
#include <cuda_runtime.h>
#include <cstdint>

// Problem constants (BATCH=4, SEQ=4096, DIM=1024)
#define B 4
#define L 4096
#define D 1024
#define NC 64                 // chunks along L
#define C  64                 // chunk length
#define NBLOCKS (B * NC)      // 256 blocks
#define NTHREADS 512          // each thread handles 2 dims

// Scratch (__device__ globals: allocation-free rule)
__device__ float2 g_totals[B * NC * D];   // chunk-end local states
__device__ float2 g_carry [B * NC * D];   // exact state entering each chunk
__device__ unsigned g_bar_count = 0;
__device__ volatile unsigned g_bar_gen = 0;

__device__ __forceinline__ float2 cmul(float2 u, float2 v) {
    return make_float2(fmaf(u.x, v.x, -u.y * v.y), fmaf(u.x, v.y, u.y * v.x));
}

__device__ __forceinline__ float2 decay(float r, float im) {
    float mag = sqrtf(fmaf(r, r, im * im));
    float s = __expf(-mag) / mag;
    return make_float2(r * s, im * s);
}

// Software grid barrier. Safe: grid=256 blocks, __launch_bounds__(512,2)
// guarantees >=2 resident blocks/SM on 148+ SMs => all blocks co-resident.
__device__ __forceinline__ void grid_barrier() {
    __syncthreads();
    if (threadIdx.x == 0) {
        __threadfence();
        unsigned my = g_bar_gen;
        if (atomicAdd(&g_bar_count, 1u) == NBLOCKS - 1) {
            g_bar_count = 0;
            __threadfence();
            g_bar_gen = my + 1;
        } else {
            while (g_bar_gen == my) { }
            __threadfence();
        }
    }
    __syncthreads();
}

__global__ void __launch_bounds__(NTHREADS, 2)
spiral_fused(const float* __restrict__ x,
             const float* __restrict__ pr, const float* __restrict__ pi,
             const float* __restrict__ ir, const float* __restrict__ ii,
             const float* __restrict__ lr, const float* __restrict__ li,
             float* __restrict__ out)
{
    const int blk   = blockIdx.x;       // = b*NC + chunk
    const int b     = blk / NC;
    const int chunk = blk % NC;
    const int d0    = threadIdx.x * 2;

    const float2 a0 = decay(pr[d0],     pi[d0]);
    const float2 a1 = decay(pr[d0 + 1], pi[d0 + 1]);
    const float c0r = ir[d0],     c0i = ii[d0];
    const float c1r = ir[d0 + 1], c1i = ii[d0 + 1];

    const size_t base = ((size_t)(b * L + chunk * C)) * D + d0;
    const float* xp = x + base;
    float* op = out + base;

    // ---- Phase 1: zero-init local scan; write Re(h_local) to out ----
    float h0r = 0.f, h0i = 0.f, h1r = 0.f, h1i = 0.f;
#pragma unroll 8
    for (int t = 0; t < C; t++) {
        float2 xv = *(const float2*)(xp + (size_t)t * D);
        float n0r = fmaf(a0.x, h0r, fmaf(-a0.y, h0i, c0r * xv.x));
        float n0i = fmaf(a0.x, h0i, fmaf( a0.y, h0r, c0i * xv.x));
        float n1r = fmaf(a1.x, h1r, fmaf(-a1.y, h1i, c1r * xv.y));
        float n1i = fmaf(a1.x, h1i, fmaf( a1.y, h1r, c1i * xv.y));
        h0r = n0r; h0i = n0i; h1r = n1r; h1i = n1i;
        *(float2*)(op + (size_t)t * D) = make_float2(h0r, h1r);
    }
    *(float4*)&g_totals[(size_t)blk * D + d0] = make_float4(h0r, h0i, h1r, h1i);

    grid_barrier();

    // ---- Carry propagation: 2048 threads, 2 chains each ----
    {
        int gid = blk * NTHREADS + threadIdx.x;
        if (gid < B * D / 2) {
            int cb  = (gid * 2) / D;
            int cd0 = (gid * 2) % D;
            float2 ca0 = decay(pr[cd0], pi[cd0]);
            float2 ca1 = decay(pr[cd0 + 1], pi[cd0 + 1]);
            float2 aC0 = ca0, aC1 = ca1;
#pragma unroll
            for (int k = 0; k < 6; k++) { aC0 = cmul(aC0, aC0); aC1 = cmul(aC1, aC1); }
            float H0r = lr[cb * D + cd0],     H0i = li[cb * D + cd0];
            float H1r = lr[cb * D + cd0 + 1], H1i = li[cb * D + cd0 + 1];
#pragma unroll
            for (int i = 0; i < NC; i++) {
                size_t idx = ((size_t)cb * NC + i) * D + cd0;
                *(float4*)&g_carry[idx] = make_float4(H0r, H0i, H1r, H1i);
                float4 tot = *(float4*)&g_totals[idx];
                float nH0r = fmaf(aC0.x, H0r, fmaf(-aC0.y, H0i, tot.x));
                float nH0i = fmaf(aC0.x, H0i, fmaf( aC0.y, H0r, tot.y));
                float nH1r = fmaf(aC1.x, H1r, fmaf(-aC1.y, H1i, tot.z));
                float nH1i = fmaf(aC1.x, H1i, fmaf( aC1.y, H1r, tot.w));
                H0r = nH0r; H0i = nH0i; H1r = nH1r; H1i = nH1i;
            }
        }
    }

    grid_barrier();

    // ---- Phase 2: add Re(a^(t-t0+1) * H) to out (no x needed) ----
    {
        float4 Hv = *(float4*)&g_carry[(size_t)blk * D + d0];
        float2 p0 = a0, p1 = a1;
#pragma unroll 8
        for (int t = 0; t < C; t++) {
            float2 v = *(float2*)(op + (size_t)t * D);
            v.x = fmaf(p0.x, Hv.x, fmaf(-p0.y, Hv.y, v.x));
            v.y = fmaf(p1.x, Hv.z, fmaf(-p1.y, Hv.w, v.y));
            *(float2*)(op + (size_t)t * D) = v;
            p0 = cmul(p0, a0);
            p1 = cmul(p1, a1);
        }
    }
}

extern "C" void kernel_launch(void* const* d_in, const int* in_sizes, int n_in,
                              void* d_out, int out_size) {
    const float* x    = (const float*)d_in[0];
    const float* p_re = (const float*)d_in[1];
    const float* p_im = (const float*)d_in[2];
    const float* i_re = (const float*)d_in[3];
    const float* i_im = (const float*)d_in[4];
    const float* lc_r = (const float*)d_in[5];
    const float* lc_i = (const float*)d_in[6];
    float* out = (float*)d_out;

    spiral_fused<<<NBLOCKS, NTHREADS>>>(x, p_re, p_im, i_re, i_im, lc_r, lc_i, out);
}